// round 3
// baseline (speedup 1.0000x reference)
#include <cuda_runtime.h>
#include <math.h>

#define Bdim 8
#define Sdim 4096
#define Edim 1024
#define Hdim 128
#define MIN_K 32

#define NTOK (Bdim * Sdim)      // 32768
#define NEMB (NTOK * Edim)      // 33554432

// ---------------- scratch (no allocations allowed) ----------------
__device__ float g_logits[NTOK];
__device__ float g_z[NTOK];
__device__ float g_mask[NTOK];

// ---------------- Kernel 1: fused scorer GEMM ----------------
// logits[t] = relu(x[t,:] @ W1 + b1) @ w2 + b2
// 128x128 tile (BN == H), BK=32, 256 threads, 8x8 micro-tile per thread.
#define BM 128
#define BK 32

__global__ __launch_bounds__(256)
void scorer_kernel(const float* __restrict__ x,
                   const float* __restrict__ w1,
                   const float* __restrict__ b1,
                   const float* __restrict__ w2,
                   const float* __restrict__ b2)
{
    __shared__ float As[BK][BM + 4];   // transposed x tile, padded
    __shared__ float Bs[BK][Hdim];     // w1 tile

    const int tid = threadIdx.x;
    const int tx = tid & 15;           // n direction (H)
    const int ty = tid >> 4;           // m direction (tokens)
    const int block_m = blockIdx.x * BM;

    // A-load mapping: thread loads one float4 of one token's K-chunk
    const int a_row = tid >> 3;        // 0..31  (+32*pass)
    const int a_k   = (tid & 7) * 4;   // 0..28
    // B-load mapping
    const int b_k = tid >> 5;          // 0..7   (+8*pass)
    const int b_n = (tid & 31) * 4;

    const float* xg = x + (size_t)block_m * Edim;

    float acc[8][8];
#pragma unroll
    for (int i = 0; i < 8; i++)
#pragma unroll
        for (int j = 0; j < 8; j++) acc[i][j] = 0.f;

    for (int k0 = 0; k0 < Edim; k0 += BK) {
#pragma unroll
        for (int p = 0; p < 4; p++) {
            int row = a_row + p * 32;
            float4 v = *(const float4*)(xg + (size_t)row * Edim + k0 + a_k);
            As[a_k + 0][row] = v.x;
            As[a_k + 1][row] = v.y;
            As[a_k + 2][row] = v.z;
            As[a_k + 3][row] = v.w;
        }
#pragma unroll
        for (int p = 0; p < 4; p++) {
            int kr = b_k + p * 8;
            *(float4*)&Bs[kr][b_n] = *(const float4*)(w1 + (size_t)(k0 + kr) * Hdim + b_n);
        }
        __syncthreads();

#pragma unroll 8
        for (int kk = 0; kk < BK; kk++) {
            float a[8], b[8];
#pragma unroll
            for (int i = 0; i < 8; i++) a[i] = As[kk][ty * 8 + i];
#pragma unroll
            for (int j = 0; j < 8; j++) b[j] = Bs[kk][tx * 8 + j];
#pragma unroll
            for (int i = 0; i < 8; i++)
#pragma unroll
                for (int j = 0; j < 8; j++)
                    acc[i][j] = fmaf(a[i], b[j], acc[i][j]);
        }
        __syncthreads();
    }

    // Epilogue: relu + dot with w2, fused. Each thread: partial over its 8 H-cols.
    float p[8];
#pragma unroll
    for (int i = 0; i < 8; i++) {
        float s = 0.f;
#pragma unroll
        for (int j = 0; j < 8; j++) {
            float h = acc[i][j] + b1[tx * 8 + j];
            h = fmaxf(h, 0.f);
            s = fmaf(h, w2[tx * 8 + j], s);
        }
        p[i] = s;
    }
    // Reduce across the 16 tx lanes (xor <= 8 stays inside each 16-lane half)
#pragma unroll
    for (int off = 8; off > 0; off >>= 1)
#pragma unroll
        for (int i = 0; i < 8; i++)
            p[i] += __shfl_xor_sync(0xffffffffu, p[i], off);

    if (tx == 0) {
        float bb = b2[0];
#pragma unroll
        for (int i = 0; i < 8; i++)
            g_logits[block_m + ty * 8 + i] = p[i] + bb;
    }
}

// ---------------- Kernel 2: expected_k + top-k threshold + mask ----------------
// One block (1024 threads) per batch row. Bitonic-sort z in smem, take k-th largest.
__global__ __launch_bounds__(1024)
void select_kernel(const float* __restrict__ u,
                   float* __restrict__ out_mask,   // may be null
                   float* __restrict__ out_ek)     // may be null
{
    __shared__ float zs[Sdim];      // 16 KB
    __shared__ float red[32];

    const int b = blockIdx.x;
    const int tid = threadIdx.x;
    const float* lrow = g_logits + b * Sdim;
    const float* urow = u + (size_t)b * Sdim;

    float sig = 0.f;
    for (int i = tid; i < Sdim; i += 1024) {
        float l = lrow[i];
        float g = -logf(-logf(urow[i]));     // gumbel, TAU==1
        float z = l + g;
        g_z[b * Sdim + i] = z;               // bitwise-consistent copy for final compare
        zs[i] = z;
        sig += 1.f / (1.f + expf(-l));
    }

    // block-reduce sigmoid sum -> expected_k
#pragma unroll
    for (int off = 16; off; off >>= 1) sig += __shfl_xor_sync(~0u, sig, off);
    if ((tid & 31) == 0) red[tid >> 5] = sig;
    __syncthreads();
    if (tid < 32) {
        float v = red[tid];
#pragma unroll
        for (int off = 16; off; off >>= 1) v += __shfl_xor_sync(~0u, v, off);
        if (tid == 0) red[0] = v;
    }
    __syncthreads();
    const float ek = red[0];
    int k = (int)ek;                 // astype(int32): truncation toward zero
    if (k < MIN_K) k = MIN_K;

    // bitonic ascending sort of zs[0..4095]
    for (int size = 2; size <= Sdim; size <<= 1) {
        for (int stride = size >> 1; stride > 0; stride >>= 1) {
            __syncthreads();
            for (int i = tid; i < Sdim; i += 1024) {
                int j = i ^ stride;
                if (j > i) {
                    float a = zs[i], c = zs[j];
                    bool up = ((i & size) == 0);
                    if ((a > c) == up) { zs[i] = c; zs[j] = a; }
                }
            }
        }
    }
    __syncthreads();

    int idx = Sdim - k;
    if (idx < 0) idx = 0;
    const float thr = zs[idx];       // k-th largest

    for (int i = tid; i < Sdim; i += 1024) {
        float m = (g_z[b * Sdim + i] >= thr) ? 1.0f : 0.0f;
        g_mask[b * Sdim + i] = m;
        if (out_mask) out_mask[b * Sdim + i] = m;
    }
    if (tid == 0 && out_ek) out_ek[b] = ek;
}

// ---------------- Kernel 3: filtered = x * mask (DRAM-bound, float4) ----------------
__global__ __launch_bounds__(512)
void filter_kernel(const float4* __restrict__ x, float4* __restrict__ out, int n4)
{
    const int stride = gridDim.x * blockDim.x;
    for (int i = blockIdx.x * blockDim.x + threadIdx.x; i < n4; i += stride) {
        float m = g_mask[i >> 8];            // 256 float4 per token (E=1024)
        float4 v = x[i];
        v.x *= m; v.y *= m; v.z *= m; v.w *= m;
        out[i] = v;
    }
}

// ---------------- launch ----------------
extern "C" void kernel_launch(void* const* d_in, const int* in_sizes, int n_in,
                              void* d_out, int out_size)
{
    const float* x  = (const float*)d_in[0];   // [B,S,E]
    const float* w1 = (const float*)d_in[1];   // [E,H]
    const float* b1 = (const float*)d_in[2];   // [H]
    const float* w2 = (const float*)d_in[3];   // [H,1]
    const float* b2 = (const float*)d_in[4];   // [1]
    const float* u  = (const float*)d_in[5];   // [B,S]
    float* out = (float*)d_out;

    // outputs concatenated in tuple order: filtered [B*S*E], mask [B*S], expected_k [B]
    float* out_mask = (out_size >= NEMB + NTOK) ? (out + NEMB) : nullptr;
    float* out_ek   = (out_size >= NEMB + NTOK + Bdim) ? (out + NEMB + NTOK) : nullptr;

    scorer_kernel<<<NTOK / BM, 256>>>(x, w1, b1, w2, b2);
    select_kernel<<<Bdim, 1024>>>(u, out_mask, out_ek);
    filter_kernel<<<4096, 512>>>((const float4*)x, (float4*)out, NEMB / 4);
}

// round 4
// speedup vs baseline: 1.0461x; 1.0461x over previous
#include <cuda_runtime.h>
#include <math.h>

#define Bdim 8
#define Sdim 4096
#define Edim 1024
#define Hdim 128
#define MIN_K 32

#define NTOK (Bdim * Sdim)      // 32768
#define NEMB (NTOK * Edim)      // 33554432

// ---------------- scratch (no allocations allowed) ----------------
__device__ float g_logits[NTOK];
__device__ float g_z[NTOK];
__device__ float g_mask[NTOK];

// ---------------- packed f32x2 helpers (sm_103a FFMA2) ----------------
#define FMA2(acc, a, b) \
    asm("fma.rn.f32x2 %0, %1, %2, %3;" : "=l"(acc) : "l"(a), "l"(b), "l"(acc))
#define DUP2(d, f) \
    asm("mov.b64 %0, {%1, %1};" : "=l"(d) : "r"(__float_as_uint(f)))
#define UNPACK2(lo, hi, v) \
    asm("mov.b64 {%0, %1}, %2;" : "=f"(lo), "=f"(hi) : "l"(v))

// ---------------- Kernel 1: fused scorer GEMM ----------------
// logits[t] = relu(x[t,:] @ W1 + b1) @ w2 + b2
// 128x128 tile (BN == H), BK=32, 256 threads, 8x8 micro-tile per thread,
// computed as 4x8 packed-f32x2 accumulators (M packed in pairs).
#define BM 128
#define BK 32

__global__ __launch_bounds__(256)
void scorer_kernel(const float* __restrict__ x,
                   const float* __restrict__ w1,
                   const float* __restrict__ b1,
                   const float* __restrict__ w2,
                   const float* __restrict__ b2)
{
    __shared__ float As[BK][BM + 4];   // transposed x tile, padded (row stride 528B, 16B-aligned)
    __shared__ float Bs[BK][Hdim];     // w1 tile

    const int tid = threadIdx.x;
    const int tx = tid & 15;           // n direction (H)
    const int ty = tid >> 4;           // m direction (tokens)
    const int block_m = blockIdx.x * BM;

    // A-load mapping: thread loads one float4 of one token's K-chunk
    const int a_row = tid >> 3;        // 0..31  (+32*pass)
    const int a_k   = (tid & 7) * 4;   // 0..28
    // B-load mapping
    const int b_k = tid >> 5;          // 0..7   (+8*pass)
    const int b_n = (tid & 31) * 4;

    const float* xg = x + (size_t)block_m * Edim;

    // acc2[p][j] holds M-rows {2p, 2p+1} (packed f32x2) for H-col j
    unsigned long long acc2[4][8];
#pragma unroll
    for (int p = 0; p < 4; p++)
#pragma unroll
        for (int j = 0; j < 8; j++) acc2[p][j] = 0ull;

    for (int k0 = 0; k0 < Edim; k0 += BK) {
#pragma unroll
        for (int p = 0; p < 4; p++) {
            int row = a_row + p * 32;
            float4 v = *(const float4*)(xg + (size_t)row * Edim + k0 + a_k);
            As[a_k + 0][row] = v.x;
            As[a_k + 1][row] = v.y;
            As[a_k + 2][row] = v.z;
            As[a_k + 3][row] = v.w;
        }
#pragma unroll
        for (int p = 0; p < 4; p++) {
            int kr = b_k + p * 8;
            *(float4*)&Bs[kr][b_n] = *(const float4*)(w1 + (size_t)(k0 + kr) * Hdim + b_n);
        }
        __syncthreads();

#pragma unroll 8
        for (int kk = 0; kk < BK; kk++) {
            // a pairs: 4 x 8-byte shared loads (8B-aligned: ty*8 floats into 528B rows)
            unsigned long long a2[4];
#pragma unroll
            for (int p = 0; p < 4; p++)
                a2[p] = *(const unsigned long long*)&As[kk][ty * 8 + 2 * p];
            // b: 8 floats, duplicated into both f32x2 lanes
            float4 blo = *(const float4*)&Bs[kk][tx * 8];
            float4 bhi = *(const float4*)&Bs[kk][tx * 8 + 4];
            unsigned long long b2[8];
            DUP2(b2[0], blo.x); DUP2(b2[1], blo.y); DUP2(b2[2], blo.z); DUP2(b2[3], blo.w);
            DUP2(b2[4], bhi.x); DUP2(b2[5], bhi.y); DUP2(b2[6], bhi.z); DUP2(b2[7], bhi.w);
#pragma unroll
            for (int p = 0; p < 4; p++)
#pragma unroll
                for (int j = 0; j < 8; j++)
                    FMA2(acc2[p][j], a2[p], b2[j]);
        }
        __syncthreads();
    }

    // Unpack to scalar 8x8 micro-tile
    float acc[8][8];
#pragma unroll
    for (int p = 0; p < 4; p++)
#pragma unroll
        for (int j = 0; j < 8; j++)
            UNPACK2(acc[2 * p][j], acc[2 * p + 1][j], acc2[p][j]);

    // Epilogue: relu + dot with w2, fused. Each thread: partial over its 8 H-cols.
    float pr[8];
#pragma unroll
    for (int i = 0; i < 8; i++) {
        float s = 0.f;
#pragma unroll
        for (int j = 0; j < 8; j++) {
            float h = acc[i][j] + b1[tx * 8 + j];
            h = fmaxf(h, 0.f);
            s = fmaf(h, w2[tx * 8 + j], s);
        }
        pr[i] = s;
    }
    // Reduce across the 16 tx lanes (xor <= 8 stays inside each 16-lane half)
#pragma unroll
    for (int off = 8; off > 0; off >>= 1)
#pragma unroll
        for (int i = 0; i < 8; i++)
            pr[i] += __shfl_xor_sync(0xffffffffu, pr[i], off);

    if (tx == 0) {
        float bb = b2[0];
#pragma unroll
        for (int i = 0; i < 8; i++)
            g_logits[block_m + ty * 8 + i] = pr[i] + bb;
    }
}

// ---------------- Kernel 2: expected_k + top-k threshold + mask ----------------
// One block (1024 threads) per batch row. Bitonic-sort z in smem, take k-th largest.
__global__ __launch_bounds__(1024)
void select_kernel(const float* __restrict__ u,
                   float* __restrict__ out_mask,   // may be null
                   float* __restrict__ out_ek)     // may be null
{
    __shared__ float zs[Sdim];      // 16 KB
    __shared__ float red[32];

    const int b = blockIdx.x;
    const int tid = threadIdx.x;
    const float* lrow = g_logits + b * Sdim;
    const float* urow = u + (size_t)b * Sdim;

    float sig = 0.f;
    for (int i = tid; i < Sdim; i += 1024) {
        float l = lrow[i];
        float g = -logf(-logf(urow[i]));     // gumbel, TAU==1
        float z = l + g;
        g_z[b * Sdim + i] = z;               // bitwise-consistent copy for final compare
        zs[i] = z;
        sig += 1.f / (1.f + expf(-l));
    }

    // block-reduce sigmoid sum -> expected_k
#pragma unroll
    for (int off = 16; off; off >>= 1) sig += __shfl_xor_sync(~0u, sig, off);
    if ((tid & 31) == 0) red[tid >> 5] = sig;
    __syncthreads();
    if (tid < 32) {
        float v = red[tid];
#pragma unroll
        for (int off = 16; off; off >>= 1) v += __shfl_xor_sync(~0u, v, off);
        if (tid == 0) red[0] = v;
    }
    __syncthreads();
    const float ek = red[0];
    int k = (int)ek;                 // astype(int32): truncation toward zero
    if (k < MIN_K) k = MIN_K;

    // bitonic ascending sort of zs[0..4095]
    for (int size = 2; size <= Sdim; size <<= 1) {
        for (int stride = size >> 1; stride > 0; stride >>= 1) {
            __syncthreads();
            for (int i = tid; i < Sdim; i += 1024) {
                int j = i ^ stride;
                if (j > i) {
                    float a = zs[i], c = zs[j];
                    bool up = ((i & size) == 0);
                    if ((a > c) == up) { zs[i] = c; zs[j] = a; }
                }
            }
        }
    }
    __syncthreads();

    int idx = Sdim - k;
    if (idx < 0) idx = 0;
    const float thr = zs[idx];       // k-th largest

    for (int i = tid; i < Sdim; i += 1024) {
        float m = (g_z[b * Sdim + i] >= thr) ? 1.0f : 0.0f;
        g_mask[b * Sdim + i] = m;
        if (out_mask) out_mask[b * Sdim + i] = m;
    }
    if (tid == 0 && out_ek) out_ek[b] = ek;
}

// ---------------- Kernel 3: filtered = x * mask (DRAM-bound, float4) ----------------
// Skip the x READ for masked-out tokens (~half): warp-coherent predicate since
// 256 consecutive float4 share one token's mask.
__global__ __launch_bounds__(512)
void filter_kernel(const float4* __restrict__ x, float4* __restrict__ out, int n4)
{
    const int stride = gridDim.x * blockDim.x;
    for (int i = blockIdx.x * blockDim.x + threadIdx.x; i < n4; i += stride) {
        float m = g_mask[i >> 8];            // 256 float4 per token (E=1024)
        float4 v;
        if (m != 0.f) {
            v = x[i];
            v.x *= m; v.y *= m; v.z *= m; v.w *= m;
        } else {
            v.x = 0.f; v.y = 0.f; v.z = 0.f; v.w = 0.f;
        }
        out[i] = v;
    }
}

// ---------------- launch ----------------
extern "C" void kernel_launch(void* const* d_in, const int* in_sizes, int n_in,
                              void* d_out, int out_size)
{
    const float* x  = (const float*)d_in[0];   // [B,S,E]
    const float* w1 = (const float*)d_in[1];   // [E,H]
    const float* b1 = (const float*)d_in[2];   // [H]
    const float* w2 = (const float*)d_in[3];   // [H,1]
    const float* b2 = (const float*)d_in[4];   // [1]
    const float* u  = (const float*)d_in[5];   // [B,S]
    float* out = (float*)d_out;

    // outputs concatenated in tuple order: filtered [B*S*E], mask [B*S], expected_k [B]
    float* out_mask = (out_size >= NEMB + NTOK) ? (out + NEMB) : nullptr;
    float* out_ek   = (out_size >= NEMB + NTOK + Bdim) ? (out + NEMB + NTOK) : nullptr;

    scorer_kernel<<<NTOK / BM, 256>>>(x, w1, b1, w2, b2);
    select_kernel<<<Bdim, 1024>>>(u, out_mask, out_ek);
    filter_kernel<<<4096, 512>>>((const float4*)x, (float4*)out, NEMB / 4);
}

// round 6
// speedup vs baseline: 1.1480x; 1.0973x over previous
#include <cuda_runtime.h>
#include <cuda_bf16.h>
#include <math.h>
#include <stdint.h>

#define Bdim 8
#define Sdim 4096
#define Edim 1024
#define Hdim 128
#define MIN_K 32

#define NTOK (Bdim * Sdim)      // 32768
#define NEMB (NTOK * Edim)      // 33554432

// ---------------- scratch (no device allocations allowed) ----------------
__device__ float g_logits[NTOK];
__device__ float g_z[NTOK];
__device__ float g_mask[NTOK];
// w1 split into 3 bf16 parts, stored [part][kblk(32)][n(128)][kk(32)] bf16
// (n-major tiles, ready for direct cp.async into [n][k] smem)
__device__ unsigned char g_w1b[3 * 32 * 128 * 32 * 2];   // 786432 B

// ---------------- PTX helpers (all baseline sm_80+, no 'a' features) ------
__device__ __forceinline__ uint32_t smem_u32(const void* p) {
    uint32_t a;
    asm("{ .reg .u64 t; cvta.to.shared.u64 t, %1; cvt.u32.u64 %0, t; }" : "=r"(a) : "l"(p));
    return a;
}
#define LDSM4(r0, r1, r2, r3, addr) \
    asm volatile("ldmatrix.sync.aligned.m8n8.x4.shared.b16 {%0,%1,%2,%3}, [%4];" \
        : "=r"(r0), "=r"(r1), "=r"(r2), "=r"(r3) : "r"(addr))
#define MMA_BF16(c0, c1, c2, c3, a0, a1, a2, a3, b0, b1) \
    asm volatile("mma.sync.aligned.m16n8k16.row.col.f32.bf16.bf16.f32 " \
        "{%0,%1,%2,%3}, {%4,%5,%6,%7}, {%8,%9}, {%0,%1,%2,%3};" \
        : "+f"(c0), "+f"(c1), "+f"(c2), "+f"(c3) \
        : "r"(a0), "r"(a1), "r"(a2), "r"(a3), "r"(b0), "r"(b1))
#define CP_ASYNC16(dst, src) \
    asm volatile("cp.async.cg.shared.global [%0], [%1], 16;" :: "r"(dst), "l"(src) : "memory")
#define CP_WAIT_ALL() asm volatile("cp.async.wait_all;" ::: "memory")

// ---------------- Kernel 0: split w1 into 3 bf16 parts, [n][k] tiles ------
__global__ __launch_bounds__(256)
void prep_w1_kernel(const float* __restrict__ w1)
{
    int idx = blockIdx.x * blockDim.x + threadIdx.x;   // 0 .. 131071
    if (idx >= 32 * 128 * 32) return;
    int kblk = idx >> 12;          // 0..31
    int n    = (idx >> 5) & 127;
    int kk   = idx & 31;
    float v = w1[(size_t)(kblk * 32 + kk) * Hdim + n];

    __nv_bfloat16 h0 = __float2bfloat16(v);
    float r1 = v - __bfloat162float(h0);
    __nv_bfloat16 h1 = __float2bfloat16(r1);
    float r2 = r1 - __bfloat162float(h1);
    __nv_bfloat16 h2 = __float2bfloat16(r2);

    __nv_bfloat16* base = (__nv_bfloat16*)g_w1b;
    base[0 * 131072 + idx] = h0;
    base[1 * 131072 + idx] = h1;
    base[2 * 131072 + idx] = h2;
}

// ---------------- Kernel 1: HMMA scorer ----------------
// C[128 tok][128 H] per CTA. K=1024 in 32 iters of BK=32.
// A = x split 3-way to bf16 in registers; B = pre-split w1 via cp.async.
// 6 passes: (a0b0)(a1b0)(a2b0)(a0b1)(a1b1)(a0b2).
// smem tiles: [128 rows][32+8 bf16] = 80 B rows (ldmatrix conflict-free).
#define ASM_OFF(st, p) ((st) * 61440u + (p) * 10240u)
#define BSM_OFF(st, p) ((st) * 61440u + 30720u + (p) * 10240u)
#define SMEM_HMMA 122880

__global__ __launch_bounds__(256, 1)
void scorer_hmma_kernel(const float* __restrict__ x,
                        const float* __restrict__ b1,
                        const float* __restrict__ w2,
                        const float* __restrict__ b2)
{
    extern __shared__ char smem[];
    const uint32_t sbase = smem_u32(smem);
    const int tid  = threadIdx.x;
    const int lane = tid & 31;
    const int wid  = tid >> 5;
    const int warp_m = (wid & 3) * 32;
    const int warp_n = (wid >> 2) * 64;
    const int block_m = blockIdx.x * 128;

    // ldmatrix per-lane offsets (bytes), constant over iters
    uint32_t a_off[2], b_off[4];
#pragma unroll
    for (int mf = 0; mf < 2; mf++)
        a_off[mf] = (uint32_t)(warp_m + mf * 16 + (lane & 15)) * 80u + (uint32_t)(lane >> 4) * 16u;
#pragma unroll
    for (int q = 0; q < 4; q++)
        b_off[q] = (uint32_t)(warp_n + q * 16 + (lane & 7) + ((lane >> 4) & 1) * 8) * 80u
                 + (uint32_t)((lane >> 3) & 1) * 16u;

    // x load mapping: row = tid>>1 (0..127), k-half = tid&1 (16 floats)
    const int xrow = tid >> 1;
    const int xkh  = tid & 1;
    const float* xg = x + (size_t)(block_m + xrow) * Edim + xkh * 16;

    // B cp.async mapping: 32 B per thread per part-tile
    const int bn  = tid >> 1;
    const int bkh = tid & 1;
    const uint32_t b_sts = (uint32_t)bn * 80u + (uint32_t)bkh * 32u;
    const size_t b_src_off = (size_t)tid * 32;

    float acc[2][8][4];
#pragma unroll
    for (int mf = 0; mf < 2; mf++)
#pragma unroll
        for (int nf = 0; nf < 8; nf++)
#pragma unroll
            for (int e = 0; e < 4; e++) acc[mf][nf][e] = 0.f;

    float xf[16];

    // ---- prologue: stage 0 ----
    {
#pragma unroll
        for (int q = 0; q < 4; q++) {
            float4 f = *(const float4*)(xg + q * 4);
            xf[q * 4 + 0] = f.x; xf[q * 4 + 1] = f.y; xf[q * 4 + 2] = f.z; xf[q * 4 + 3] = f.w;
        }
#pragma unroll
        for (int p = 0; p < 3; p++) {
            const char* src = (const char*)g_w1b + (size_t)p * 262144 + b_src_off;
            CP_ASYNC16(sbase + BSM_OFF(0, p) + b_sts, src);
            CP_ASYNC16(sbase + BSM_OFF(0, p) + b_sts + 16, src + 16);
        }
        // convert + STS A stage 0
        unsigned short s0[16], s1[16], s2[16];
#pragma unroll
        for (int e = 0; e < 16; e++) {
            __nv_bfloat16 h0 = __float2bfloat16(xf[e]);
            float r1 = xf[e] - __bfloat162float(h0);
            __nv_bfloat16 h1 = __float2bfloat16(r1);
            float r2 = r1 - __bfloat162float(h1);
            __nv_bfloat16 h2 = __float2bfloat16(r2);
            s0[e] = __bfloat16_as_ushort(h0);
            s1[e] = __bfloat16_as_ushort(h1);
            s2[e] = __bfloat16_as_ushort(h2);
        }
        const uint32_t a_sts = (uint32_t)xrow * 80u + (uint32_t)xkh * 32u;
        unsigned short* sp[3] = {s0, s1, s2};
#pragma unroll
        for (int p = 0; p < 3; p++) {
            uint4 lo = make_uint4((uint32_t)sp[p][0] | ((uint32_t)sp[p][1] << 16),
                                  (uint32_t)sp[p][2] | ((uint32_t)sp[p][3] << 16),
                                  (uint32_t)sp[p][4] | ((uint32_t)sp[p][5] << 16),
                                  (uint32_t)sp[p][6] | ((uint32_t)sp[p][7] << 16));
            uint4 hi = make_uint4((uint32_t)sp[p][8]  | ((uint32_t)sp[p][9]  << 16),
                                  (uint32_t)sp[p][10] | ((uint32_t)sp[p][11] << 16),
                                  (uint32_t)sp[p][12] | ((uint32_t)sp[p][13] << 16),
                                  (uint32_t)sp[p][14] | ((uint32_t)sp[p][15] << 16));
            *(uint4*)(smem + ASM_OFF(0, p) + a_sts)      = lo;
            *(uint4*)(smem + ASM_OFF(0, p) + a_sts + 16) = hi;
        }
        CP_WAIT_ALL();
        __syncthreads();
    }

    // ---- main loop ----
    for (int it = 0; it < 32; it++) {
        const int st = it & 1;
        const int nst = st ^ 1;

        if (it < 31) {
            // prefetch next x (LDG latency hidden by HMMA below)
#pragma unroll
            for (int q = 0; q < 4; q++) {
                float4 f = *(const float4*)(xg + (it + 1) * 32 + q * 4);
                xf[q * 4 + 0] = f.x; xf[q * 4 + 1] = f.y; xf[q * 4 + 2] = f.z; xf[q * 4 + 3] = f.w;
            }
            // async B for next stage
#pragma unroll
            for (int p = 0; p < 3; p++) {
                const char* src = (const char*)g_w1b + (size_t)p * 262144
                                + (size_t)(it + 1) * 8192 + b_src_off;
                CP_ASYNC16(sbase + BSM_OFF(nst, p) + b_sts, src);
                CP_ASYNC16(sbase + BSM_OFF(nst, p) + b_sts + 16, src + 16);
            }
        }

        // ---- HMMA: 2 k16-steps x 6 passes with B-frag reuse ----
#pragma unroll
        for (int k16 = 0; k16 < 2; k16++) {
            const uint32_t kb = (uint32_t)k16 * 32u;
#pragma unroll
            for (int pb = 0; pb < 3; pb++) {
                uint32_t br[16];
#pragma unroll
                for (int q = 0; q < 4; q++)
                    LDSM4(br[q * 4 + 0], br[q * 4 + 1], br[q * 4 + 2], br[q * 4 + 3],
                          sbase + BSM_OFF(st, pb) + b_off[q] + kb);
                const int na = 3 - pb;   // pb0:{a0,a1,a2} pb1:{a0,a1} pb2:{a0}
#pragma unroll
                for (int pa = 0; pa < 3; pa++) {
                    if (pa >= na) break;
                    uint32_t ar[8];
                    LDSM4(ar[0], ar[1], ar[2], ar[3], sbase + ASM_OFF(st, pa) + a_off[0] + kb);
                    LDSM4(ar[4], ar[5], ar[6], ar[7], sbase + ASM_OFF(st, pa) + a_off[1] + kb);
#pragma unroll
                    for (int mf = 0; mf < 2; mf++)
#pragma unroll
                        for (int nf = 0; nf < 8; nf++) {
                            const int q = nf >> 1, pr = nf & 1;
                            MMA_BF16(acc[mf][nf][0], acc[mf][nf][1], acc[mf][nf][2], acc[mf][nf][3],
                                     ar[mf * 4 + 0], ar[mf * 4 + 1], ar[mf * 4 + 2], ar[mf * 4 + 3],
                                     br[q * 4 + pr * 2], br[q * 4 + pr * 2 + 1]);
                        }
                }
            }
        }

        if (it < 31) {
            // convert prefetched x, store to next stage
            unsigned short s0[16], s1[16], s2[16];
#pragma unroll
            for (int e = 0; e < 16; e++) {
                __nv_bfloat16 h0 = __float2bfloat16(xf[e]);
                float r1 = xf[e] - __bfloat162float(h0);
                __nv_bfloat16 h1 = __float2bfloat16(r1);
                float r2 = r1 - __bfloat162float(h1);
                __nv_bfloat16 h2 = __float2bfloat16(r2);
                s0[e] = __bfloat16_as_ushort(h0);
                s1[e] = __bfloat16_as_ushort(h1);
                s2[e] = __bfloat16_as_ushort(h2);
            }
            const uint32_t a_sts = (uint32_t)xrow * 80u + (uint32_t)xkh * 32u;
            unsigned short* sp[3] = {s0, s1, s2};
#pragma unroll
            for (int p = 0; p < 3; p++) {
                uint4 lo = make_uint4((uint32_t)sp[p][0] | ((uint32_t)sp[p][1] << 16),
                                      (uint32_t)sp[p][2] | ((uint32_t)sp[p][3] << 16),
                                      (uint32_t)sp[p][4] | ((uint32_t)sp[p][5] << 16),
                                      (uint32_t)sp[p][6] | ((uint32_t)sp[p][7] << 16));
                uint4 hi = make_uint4((uint32_t)sp[p][8]  | ((uint32_t)sp[p][9]  << 16),
                                      (uint32_t)sp[p][10] | ((uint32_t)sp[p][11] << 16),
                                      (uint32_t)sp[p][12] | ((uint32_t)sp[p][13] << 16),
                                      (uint32_t)sp[p][14] | ((uint32_t)sp[p][15] << 16));
                *(uint4*)(smem + ASM_OFF(nst, p) + a_sts)      = lo;
                *(uint4*)(smem + ASM_OFF(nst, p) + a_sts + 16) = hi;
            }
        }
        CP_WAIT_ALL();
        __syncthreads();
    }

    // ---- epilogue: relu + dot(w2) from C fragments ----
    float b1v[16], w2v[16];
#pragma unroll
    for (int nf = 0; nf < 8; nf++)
#pragma unroll
        for (int j = 0; j < 2; j++) {
            const int n = warp_n + nf * 8 + 2 * (lane & 3) + j;
            b1v[nf * 2 + j] = b1[n];
            w2v[nf * 2 + j] = w2[n];
        }

    float* red = (float*)smem;   // [2][128] — stage-0 A buffer is free now (last iter used stage 1)
#pragma unroll
    for (int mf = 0; mf < 2; mf++)
#pragma unroll
        for (int half = 0; half < 2; half++) {
            float s = 0.f;
#pragma unroll
            for (int nf = 0; nf < 8; nf++)
#pragma unroll
                for (int j = 0; j < 2; j++) {
                    float v = acc[mf][nf][half * 2 + j] + b1v[nf * 2 + j];
                    v = fmaxf(v, 0.f);
                    s = fmaf(v, w2v[nf * 2 + j], s);
                }
            s += __shfl_xor_sync(0xffffffffu, s, 1);
            s += __shfl_xor_sync(0xffffffffu, s, 2);
            if ((lane & 3) == 0)
                red[(wid >> 2) * 128 + warp_m + mf * 16 + half * 8 + (lane >> 2)] = s;
        }
    __syncthreads();
    if (tid < 128)
        g_logits[block_m + tid] = red[tid] + red[128 + tid] + b2[0];
}

// ---------------- Kernel 2: expected_k + top-k threshold + mask ----------------
__global__ __launch_bounds__(1024)
void select_kernel(const float* __restrict__ u,
                   float* __restrict__ out_mask,
                   float* __restrict__ out_ek)
{
    __shared__ float zs[Sdim];
    __shared__ float red[32];

    const int b = blockIdx.x;
    const int tid = threadIdx.x;
    const float* lrow = g_logits + b * Sdim;
    const float* urow = u + (size_t)b * Sdim;

    float sig = 0.f;
    for (int i = tid; i < Sdim; i += 1024) {
        float l = lrow[i];
        float g = -logf(-logf(urow[i]));
        float z = l + g;
        g_z[b * Sdim + i] = z;
        zs[i] = z;
        sig += 1.f / (1.f + expf(-l));
    }
#pragma unroll
    for (int off = 16; off; off >>= 1) sig += __shfl_xor_sync(~0u, sig, off);
    if ((tid & 31) == 0) red[tid >> 5] = sig;
    __syncthreads();
    if (tid < 32) {
        float v = red[tid];
#pragma unroll
        for (int off = 16; off; off >>= 1) v += __shfl_xor_sync(~0u, v, off);
        if (tid == 0) red[0] = v;
    }
    __syncthreads();
    const float ek = red[0];
    int k = (int)ek;
    if (k < MIN_K) k = MIN_K;

    for (int size = 2; size <= Sdim; size <<= 1) {
        for (int stride = size >> 1; stride > 0; stride >>= 1) {
            __syncthreads();
            for (int i = tid; i < Sdim; i += 1024) {
                int j = i ^ stride;
                if (j > i) {
                    float a = zs[i], c = zs[j];
                    bool up = ((i & size) == 0);
                    if ((a > c) == up) { zs[i] = c; zs[j] = a; }
                }
            }
        }
    }
    __syncthreads();

    int idx = Sdim - k;
    if (idx < 0) idx = 0;
    const float thr = zs[idx];

    for (int i = tid; i < Sdim; i += 1024) {
        float m = (g_z[b * Sdim + i] >= thr) ? 1.0f : 0.0f;
        g_mask[b * Sdim + i] = m;
        if (out_mask) out_mask[b * Sdim + i] = m;
    }
    if (tid == 0 && out_ek) out_ek[b] = ek;
}

// ---------------- Kernel 3: filtered = x * mask ----------------
__global__ __launch_bounds__(512)
void filter_kernel(const float4* __restrict__ x, float4* __restrict__ out, int n4)
{
    const int stride = gridDim.x * blockDim.x;
    for (int i = blockIdx.x * blockDim.x + threadIdx.x; i < n4; i += stride) {
        float m = g_mask[i >> 8];
        float4 v;
        if (m != 0.f) {
            v = x[i];
            v.x *= m; v.y *= m; v.z *= m; v.w *= m;
        } else {
            v.x = 0.f; v.y = 0.f; v.z = 0.f; v.w = 0.f;
        }
        out[i] = v;
    }
}

// ---------------- launch ----------------
extern "C" void kernel_launch(void* const* d_in, const int* in_sizes, int n_in,
                              void* d_out, int out_size)
{
    const float* x  = (const float*)d_in[0];
    const float* w1 = (const float*)d_in[1];
    const float* b1 = (const float*)d_in[2];
    const float* w2 = (const float*)d_in[3];
    const float* b2 = (const float*)d_in[4];
    const float* u  = (const float*)d_in[5];
    float* out = (float*)d_out;

    float* out_mask = (out_size >= NEMB + NTOK) ? (out + NEMB) : nullptr;
    float* out_ek   = (out_size >= NEMB + NTOK + Bdim) ? (out + NEMB + NTOK) : nullptr;

    cudaFuncSetAttribute(scorer_hmma_kernel,
                         cudaFuncAttributeMaxDynamicSharedMemorySize, SMEM_HMMA);

    prep_w1_kernel<<<512, 256>>>(w1);
    scorer_hmma_kernel<<<NTOK / 128, 256, SMEM_HMMA>>>(x, b1, w2, b2);
    select_kernel<<<Bdim, 1024>>>(u, out_mask, out_ek);
    filter_kernel<<<4096, 512>>>((const float4*)x, (float4*)out, NEMB / 4);
}